// round 2
// baseline (speedup 1.0000x reference)
#include <cuda_runtime.h>
#include <cuda_bf16.h>
#include <math.h>

#define BB 2
#define NROI 625            // per batch (25 anchors * 5 * 5)
#define NTOT 1250
#define FF 7
#define CC 512
#define DD 25088            // 512*49
#define H1 200
#define H2 100
#define KC 17
#define NKEY 2402           // 7*7*7*7 (=2401) combos + 1 empty, per batch
#define TOTKEY 4804
#define MAXROWS 1250
#define KSPLIT 49           // 49 * 512 = 25088
#define KCHUNK 512

// ---------------- scratch (static device globals; no allocation) ----------------
__device__ float g_A[(size_t)MAXROWS * DD];          // pooled rows (unique), row-major [r][c*49+i*7+j]
__device__ float g_P[(size_t)KSPLIT * MAXROWS * H1]; // split-K partials
__device__ float g_h1[MAXROWS * H1];
__device__ float g_out85[MAXROWS * 85];
__device__ int   g_used[TOTKEY];
__device__ int   g_rowOf[TOTKEY];
__device__ int   g_keyOfRow[TOTKEY];
__device__ int   g_roiKey[NTOT];
__device__ int   g_roiRow[NTOT];
__device__ int   g_M[1];

// ---------------- kernel 1: zero flags ----------------
__global__ void zero_kernel() {
    int i = blockIdx.x * blockDim.x + threadIdx.x;
    if (i < TOTKEY) g_used[i] = 0;
}

// ---------------- kernel 2: anchor decode + coord pipeline -> key ----------------
__global__ void boxes_kernel(const float* __restrict__ regcls,
                             const float* __restrict__ wan,
                             const float* __restrict__ han,
                             const float* __restrict__ xan,
                             const float* __restrict__ yan) {
    int idx = blockIdx.x * blockDim.x + threadIdx.x;
    if (idx >= NTOT) return;
    int b = idx / NROI;
    int n = idx % NROI;
    const float* reg = regcls + (size_t)b * 5 * NROI;
    float r0 = reg[n];
    float r1 = reg[NROI + n];
    float r2 = reg[2 * NROI + n];
    float r3 = reg[3 * NROI + n];
    float w = wan[n], h = han[n], xa = xan[n], ya = yan[n];

    float wreg = expf(r2) * w;
    float hreg = expf(r3) * h;
    float xreg = r0 * w + xa;
    float yreg = r1 * h + ya;
    float xis = xreg - wreg * 0.5f;
    float yis = yreg - hreg * 0.5f;
    float xfs = xreg + wreg * 0.5f;
    float yfs = yreg + hreg * 0.5f;

    float c0 = floorf(fmaxf(xis, 0.f));
    float c1 = floorf(fmaxf(yis, 0.f));
    float c2 = fminf(ceilf(xfs), 295.f);
    float c3 = fmaxf(ceilf(yfs), 295.f);   // (sic) max, as in source

    bool on = (xis < 296.f) && (yis < 296.f) && (xfs >= 0.f) && (yfs >= 0.f);

#define CONV_STEP(L) { c0 = fmaxf(c0 - 1.f, 0.f); c1 = fmaxf(c1 - 1.f, 0.f); \
                       c2 = fminf(c2, (float)(L)); c3 = fminf(c3, (float)(L)); }
#define MP_STEP()    { c0 = floorf(c0 * 0.5f); c1 = floorf(c1 * 0.5f); \
                       c2 = floorf(c2 * 0.5f); c3 = floorf(c3 * 0.5f); }
    CONV_STEP(293); CONV_STEP(291); MP_STEP();
    CONV_STEP(143); CONV_STEP(141); MP_STEP();
    CONV_STEP(68);  CONV_STEP(66);  CONV_STEP(64); MP_STEP();
    CONV_STEP(29);  CONV_STEP(27);  CONV_STEP(25); MP_STEP();
    CONV_STEP(10);  CONV_STEP(8);   CONV_STEP(6);
#undef CONV_STEP
#undef MP_STEP

    int xi = (int)c0, yi = (int)c1, xf = (int)c2, yf = (int)c3;
    int wx = xf + 1 - xi, wy = yf + 1 - yi;
    int kid;
    if (!on || wx <= 0 || wy <= 0 || xi > 6 || yi > 6 || xf < 0 || yf < 0) {
        kid = 2401;  // canonical empty row (all pooled = 0)
    } else {
        kid = ((xi * 7 + yi) * 7 + xf) * 7 + yf;  // all components in [0,6]
    }
    int e = b * NKEY + kid;
    g_roiKey[idx] = e;
    g_used[e] = 1;
}

// ---------------- kernel 3: deterministic compaction (one block) ----------------
__global__ void compact_kernel() {
    __shared__ int wsum[32];
    int tid = threadIdx.x;
    int base = tid * 5;  // 1024 * 5 = 5120 >= 4804
    int loc[5];
    int cnt = 0;
#pragma unroll
    for (int u = 0; u < 5; u++) {
        int e = base + u;
        int v = (e < TOTKEY) ? g_used[e] : 0;
        loc[u] = v;
        cnt += v;
    }
    int lane = tid & 31, wid = tid >> 5;
    int x = cnt;
    for (int d = 1; d < 32; d <<= 1) {
        int y = __shfl_up_sync(0xffffffffu, x, d);
        if (lane >= d) x += y;
    }
    if (lane == 31) wsum[wid] = x;
    __syncthreads();
    if (wid == 0) {
        int w = wsum[lane];
        for (int d = 1; d < 32; d <<= 1) {
            int y = __shfl_up_sync(0xffffffffu, w, d);
            if (lane >= d) w += y;
        }
        wsum[lane] = w;
    }
    __syncthreads();
    int off = x - cnt + (wid ? wsum[wid - 1] : 0);
#pragma unroll
    for (int u = 0; u < 5; u++) {
        int e = base + u;
        if (e < TOTKEY) {
            if (loc[u]) {
                g_rowOf[e] = off;
                g_keyOfRow[off] = e;
                off++;
            } else {
                g_rowOf[e] = -1;
            }
        }
    }
    if (tid == 1023) g_M[0] = off;
}

// ---------------- kernel 4: ROI -> unique row ----------------
__global__ void assign_kernel() {
    int idx = blockIdx.x * blockDim.x + threadIdx.x;
    if (idx >= NTOT) return;
    g_roiRow[idx] = g_rowOf[g_roiKey[idx]];
}

// ---------------- kernel 5: build pooled row per unique key ----------------
__global__ void pool_kernel(const float* __restrict__ cf) {
    int r = blockIdx.x;
    if (r >= g_M[0]) return;
    int e = g_keyOfRow[r];
    int b = e / NKEY;
    int kid = e % NKEY;
    float* Arow = g_A + (size_t)r * DD;
    if (kid == 2401) {
        for (int k = threadIdx.x; k < DD; k += 256) Arow[k] = 0.f;
        return;
    }
    int yf = kid % 7;
    int xf = (kid / 7) % 7;
    int yi = (kid / 49) % 7;
    int xi = kid / 343;
    int wx = xf + 1 - xi, wy = yf + 1 - yi;  // both >= 1 by construction
    int bx[8], by[8];
#pragma unroll
    for (int ii = 0; ii < 8; ii++) {
        bx[ii] = xi + (ii * wx) / 7;
        by[ii] = yi + (ii * wy) / 7;
    }
    for (int c = threadIdx.x; c < CC; c += 256) {
        const float* f = cf + ((size_t)b * CC + c) * 49;
        float v[49];
#pragma unroll
        for (int p = 0; p < 49; p++) v[p] = f[p];
#pragma unroll
        for (int i = 0; i < 7; i++) {
            int x0 = bx[i], x1 = bx[i + 1];
#pragma unroll
            for (int j = 0; j < 7; j++) {
                int y0 = by[j], y1 = by[j + 1];
                float m = -3.0e38f;
                for (int xx = x0; xx < x1; xx++)
                    for (int yy = y0; yy < y1; yy++)
                        m = fmaxf(m, v[xx * 7 + yy]);
                Arow[c * 49 + i * 7 + j] = (x1 > x0 && y1 > y0) ? m : 0.f;
            }
        }
    }
}

// ---------------- kernel 6: split-K GEMM  h1_partial = A @ w1^T ----------------
__global__ void __launch_bounds__(256) gemm1_kernel(const float* __restrict__ w1) {
    const int M = g_M[0];
    const int rt = blockIdx.y;
    if (rt * 8 >= M) return;
    const int k0 = blockIdx.x * KCHUNK;
    __shared__ __align__(16) float sA[8 * KCHUNK];
    __shared__ __align__(16) float sW[H1 * 36];
    const int tid = threadIdx.x;
    for (int idx = tid; idx < 8 * KCHUNK; idx += 256) {
        int rr = idx >> 9, k = idx & 511;
        int g = rt * 8 + rr;
        sA[idx] = (g < M) ? g_A[(size_t)g * DD + k0 + k] : 0.f;
    }
    float acc[8] = {0, 0, 0, 0, 0, 0, 0, 0};
    for (int kt = 0; kt < 16; kt++) {
        __syncthreads();
        for (int idx = tid; idx < H1 * 32; idx += 256) {
            int o = idx >> 5, kk = idx & 31;
            sW[o * 36 + kk] = w1[(size_t)o * DD + k0 + kt * 32 + kk];
        }
        __syncthreads();
        if (tid < H1) {
#pragma unroll
            for (int q = 0; q < 8; q++) {
                float4 wv = *reinterpret_cast<float4*>(&sW[tid * 36 + q * 4]);
#pragma unroll
                for (int rr = 0; rr < 8; rr++) {
                    float4 av = *reinterpret_cast<float4*>(&sA[rr * KCHUNK + kt * 32 + q * 4]);
                    acc[rr] += av.x * wv.x + av.y * wv.y + av.z * wv.z + av.w * wv.w;
                }
            }
        }
    }
    if (tid < H1) {
#pragma unroll
        for (int rr = 0; rr < 8; rr++) {
            int g = rt * 8 + rr;
            if (g < MAXROWS)
                g_P[((size_t)blockIdx.x * MAXROWS + g) * H1 + tid] = acc[rr];
        }
    }
}

// ---------------- kernel 7: reduce split-K + bias + relu ----------------
__global__ void reduce1_kernel(const float* __restrict__ b1) {
    int idx = blockIdx.x * blockDim.x + threadIdx.x;
    if (idx >= NTOT * H1) return;
    int r = idx / H1;
    if (r >= g_M[0]) return;
    int o = idx % H1;
    float s = b1[o];
#pragma unroll
    for (int ks = 0; ks < KSPLIT; ks++)
        s += g_P[((size_t)ks * MAXROWS + r) * H1 + o];
    g_h1[idx] = fmaxf(s, 0.f);
}

// ---------------- kernel 8: small MLP tail per unique row ----------------
__global__ void mlp_kernel(const float* __restrict__ w2, const float* __restrict__ b2,
                           const float* __restrict__ w3, const float* __restrict__ b3,
                           const float* __restrict__ w4, const float* __restrict__ b4) {
    int r = blockIdx.x;
    if (r >= g_M[0]) return;
    __shared__ float h1s[H1];
    __shared__ float h2s[H2];
    for (int k = threadIdx.x; k < H1; k += 128) h1s[k] = g_h1[r * H1 + k];
    __syncthreads();
    int t = threadIdx.x;
    if (t < H2) {
        float s = b2[t];
        const float* wr = w2 + t * H1;
#pragma unroll 4
        for (int k = 0; k < H1; k++) s += h1s[k] * wr[k];
        h2s[t] = fmaxf(s, 0.f);
    }
    __syncthreads();
    if (t < 85) {
        float s;
        const float* wr;
        if (t < KC) { s = b3[t];      wr = w3 + t * H2; }
        else        { s = b4[t - KC]; wr = w4 + (t - KC) * H2; }
#pragma unroll 4
        for (int k = 0; k < H2; k++) s += h2s[k] * wr[k];
        g_out85[r * 85 + t] = s;
    }
}

// ---------------- kernel 9: scatter unique rows to all ROIs ----------------
__global__ void scatter_kernel(float* __restrict__ out) {
    int idx = blockIdx.x * blockDim.x + threadIdx.x;
    if (idx >= NTOT * 85) return;
    int bn = idx / 85;
    int q = idx % 85;
    int r = g_roiRow[bn];
    float val = g_out85[r * 85 + q];
    if (q < KC) {
        out[bn * KC + q] = val;                           // z1: (B,A,G,G,17)
    } else {
        int k = (q - KC) / KC, cls = (q - KC) % KC;
        int b = bn / NROI, n = bn % NROI;
        out[NTOT * KC + ((b * 4 + k) * NROI + n) * KC + cls];  // compute idx
        out[NTOT * KC + (((b * 4 + k) * NROI + n) * KC + cls)] = val; // z3: (B,4,A,G,G,17)
    }
}

// ---------------- launch ----------------
extern "C" void kernel_launch(void* const* d_in, const int* in_sizes, int n_in,
                              void* d_out, int out_size) {
    const float* cfeats = (const float*)d_in[0];
    const float* regcls = (const float*)d_in[1];
    const float* wan    = (const float*)d_in[2];
    const float* han    = (const float*)d_in[3];
    const float* xan    = (const float*)d_in[4];
    const float* yan    = (const float*)d_in[5];
    const float* w1     = (const float*)d_in[6];
    const float* b1     = (const float*)d_in[7];
    const float* w2     = (const float*)d_in[8];
    const float* b2     = (const float*)d_in[9];
    const float* w3     = (const float*)d_in[10];
    const float* b3     = (const float*)d_in[11];
    const float* w4     = (const float*)d_in[12];
    const float* b4     = (const float*)d_in[13];
    float* out = (float*)d_out;

    zero_kernel<<<(TOTKEY + 255) / 256, 256>>>();
    boxes_kernel<<<(NTOT + 255) / 256, 256>>>(regcls, wan, han, xan, yan);
    compact_kernel<<<1, 1024>>>();
    assign_kernel<<<(NTOT + 255) / 256, 256>>>();
    pool_kernel<<<MAXROWS, 256>>>(cfeats);
    {
        dim3 grid(KSPLIT, (MAXROWS + 7) / 8);
        gemm1_kernel<<<grid, 256>>>(w1);
    }
    reduce1_kernel<<<(NTOT * H1 + 255) / 256, 256>>>(b1);
    mlp_kernel<<<MAXROWS, 128>>>(w2, b2, w3, b3, w4, b4);
    scatter_kernel<<<(NTOT * 85 + 255) / 256, 256>>>(out);
}

// round 3
// speedup vs baseline: 1.4946x; 1.4946x over previous
#include <cuda_runtime.h>
#include <cuda_bf16.h>
#include <math.h>
#include <stdint.h>

#define BB 2
#define NROI 625            // per batch (25 anchors * 5 * 5)
#define NTOT 1250
#define FF 7
#define CC 512
#define DD 25088            // 512*49
#define H1 200
#define H2 100
#define KC 17
#define NKEY 2402           // 7*7*7*7 (=2401) combos + 1 empty, per batch
#define TOTKEY 4804
#define MAXROWS 1250
#define KSPLIT 49           // 49 * 512 = 25088
#define KCHUNK 512

// ---------------- scratch (static device globals; no allocation) ----------------
__device__ float g_A[(size_t)MAXROWS * DD];          // pooled rows (unique)
__device__ float g_P[(size_t)KSPLIT * MAXROWS * H1]; // split-K partials
__device__ float g_h1[MAXROWS * H1];
__device__ float g_out85[MAXROWS * 85];
__device__ int   g_used[TOTKEY];
__device__ int   g_rowOf[TOTKEY];
__device__ int   g_keyOfRow[TOTKEY];
__device__ int   g_roiKey[NTOT];
__device__ int   g_roiRow[NTOT];
__device__ int   g_M[1];

// ---------------- kernel 1: zero flags ----------------
__global__ void zero_kernel() {
    int i = blockIdx.x * blockDim.x + threadIdx.x;
    if (i < TOTKEY) g_used[i] = 0;
}

// ---------------- kernel 2: anchor decode + coord pipeline -> key ----------------
__global__ void boxes_kernel(const float* __restrict__ regcls,
                             const float* __restrict__ wan,
                             const float* __restrict__ han,
                             const float* __restrict__ xan,
                             const float* __restrict__ yan) {
    int idx = blockIdx.x * blockDim.x + threadIdx.x;
    if (idx >= NTOT) return;
    int b = idx / NROI;
    int n = idx % NROI;
    const float* reg = regcls + (size_t)b * 5 * NROI;
    float r0 = reg[n];
    float r1 = reg[NROI + n];
    float r2 = reg[2 * NROI + n];
    float r3 = reg[3 * NROI + n];
    float w = wan[n], h = han[n], xa = xan[n], ya = yan[n];

    float wreg = expf(r2) * w;
    float hreg = expf(r3) * h;
    float xreg = r0 * w + xa;
    float yreg = r1 * h + ya;
    float xis = xreg - wreg * 0.5f;
    float yis = yreg - hreg * 0.5f;
    float xfs = xreg + wreg * 0.5f;
    float yfs = yreg + hreg * 0.5f;

    float c0 = floorf(fmaxf(xis, 0.f));
    float c1 = floorf(fmaxf(yis, 0.f));
    float c2 = fminf(ceilf(xfs), 295.f);
    float c3 = fmaxf(ceilf(yfs), 295.f);   // (sic) max, as in source

    bool on = (xis < 296.f) && (yis < 296.f) && (xfs >= 0.f) && (yfs >= 0.f);

#define CONV_STEP(L) { c0 = fmaxf(c0 - 1.f, 0.f); c1 = fmaxf(c1 - 1.f, 0.f); \
                       c2 = fminf(c2, (float)(L)); c3 = fminf(c3, (float)(L)); }
#define MP_STEP()    { c0 = floorf(c0 * 0.5f); c1 = floorf(c1 * 0.5f); \
                       c2 = floorf(c2 * 0.5f); c3 = floorf(c3 * 0.5f); }
    CONV_STEP(293); CONV_STEP(291); MP_STEP();
    CONV_STEP(143); CONV_STEP(141); MP_STEP();
    CONV_STEP(68);  CONV_STEP(66);  CONV_STEP(64); MP_STEP();
    CONV_STEP(29);  CONV_STEP(27);  CONV_STEP(25); MP_STEP();
    CONV_STEP(10);  CONV_STEP(8);   CONV_STEP(6);
#undef CONV_STEP
#undef MP_STEP

    int xi = (int)c0, yi = (int)c1, xf = (int)c2, yf = (int)c3;
    int wx = xf + 1 - xi, wy = yf + 1 - yi;
    int kid;
    if (!on || wx <= 0 || wy <= 0 || xi > 6 || yi > 6 || xf < 0 || yf < 0) {
        kid = 2401;  // canonical empty row (all pooled = 0)
    } else {
        kid = ((xi * 7 + yi) * 7 + xf) * 7 + yf;  // all components in [0,6]
    }
    int e = b * NKEY + kid;
    g_roiKey[idx] = e;
    g_used[e] = 1;
}

// ---------------- kernel 3: deterministic compaction (one block) ----------------
__global__ void compact_kernel() {
    __shared__ int wsum[32];
    int tid = threadIdx.x;
    int base = tid * 5;  // 1024 * 5 = 5120 >= 4804
    int loc[5];
    int cnt = 0;
#pragma unroll
    for (int u = 0; u < 5; u++) {
        int e = base + u;
        int v = (e < TOTKEY) ? g_used[e] : 0;
        loc[u] = v;
        cnt += v;
    }
    int lane = tid & 31, wid = tid >> 5;
    int x = cnt;
    for (int d = 1; d < 32; d <<= 1) {
        int y = __shfl_up_sync(0xffffffffu, x, d);
        if (lane >= d) x += y;
    }
    if (lane == 31) wsum[wid] = x;
    __syncthreads();
    if (wid == 0) {
        int w = wsum[lane];
        for (int d = 1; d < 32; d <<= 1) {
            int y = __shfl_up_sync(0xffffffffu, w, d);
            if (lane >= d) w += y;
        }
        wsum[lane] = w;
    }
    __syncthreads();
    int off = x - cnt + (wid ? wsum[wid - 1] : 0);
#pragma unroll
    for (int u = 0; u < 5; u++) {
        int e = base + u;
        if (e < TOTKEY) {
            if (loc[u]) {
                g_rowOf[e] = off;
                g_keyOfRow[off] = e;
                off++;
            } else {
                g_rowOf[e] = -1;
            }
        }
    }
    if (tid == 1023) g_M[0] = off;
}

// ---------------- kernel 4: ROI -> unique row ----------------
__global__ void assign_kernel() {
    int idx = blockIdx.x * blockDim.x + threadIdx.x;
    if (idx >= NTOT) return;
    g_roiRow[idx] = g_rowOf[g_roiKey[idx]];
}

// ---------------- kernel 5: build pooled row per unique key ----------------
__global__ void pool_kernel(const float* __restrict__ cf) {
    int r = blockIdx.x;
    if (r >= g_M[0]) return;
    int e = g_keyOfRow[r];
    int b = e / NKEY;
    int kid = e % NKEY;
    float* Arow = g_A + (size_t)r * DD;
    if (kid == 2401) {
        for (int k = threadIdx.x; k < DD; k += 256) Arow[k] = 0.f;
        return;
    }
    int yf = kid % 7;
    int xf = (kid / 7) % 7;
    int yi = (kid / 49) % 7;
    int xi = kid / 343;
    int wx = xf + 1 - xi, wy = yf + 1 - yi;  // both >= 1 by construction
    int bx[8], by[8];
#pragma unroll
    for (int ii = 0; ii < 8; ii++) {
        bx[ii] = xi + (ii * wx) / 7;
        by[ii] = yi + (ii * wy) / 7;
    }
    for (int c = threadIdx.x; c < CC; c += 256) {
        const float* f = cf + ((size_t)b * CC + c) * 49;
        float v[49];
#pragma unroll
        for (int p = 0; p < 49; p++) v[p] = f[p];
#pragma unroll
        for (int i = 0; i < 7; i++) {
            int x0 = bx[i], x1 = bx[i + 1];
#pragma unroll
            for (int j = 0; j < 7; j++) {
                int y0 = by[j], y1 = by[j + 1];
                float m = -3.0e38f;
                for (int xx = x0; xx < x1; xx++)
                    for (int yy = y0; yy < y1; yy++)
                        m = fmaxf(m, v[xx * 7 + yy]);
                Arow[c * 49 + i * 7 + j] = (x1 > x0 && y1 > y0) ? m : 0.f;
            }
        }
    }
}

// ---------------- tf32 helpers ----------------
__device__ __forceinline__ float tf32r(float x) {
    uint32_t u;
    asm("cvt.rna.tf32.f32 %0, %1;" : "=r"(u) : "f"(x));
    return __uint_as_float(u);
}
__device__ __forceinline__ void cvt4(float4& v) {
    v.x = tf32r(v.x); v.y = tf32r(v.y); v.z = tf32r(v.z); v.w = tf32r(v.w);
}
__device__ __forceinline__ void mma_tf32(float& d0, float& d1, float& d2, float& d3,
                                         uint32_t a0, uint32_t a1, uint32_t a2, uint32_t a3,
                                         uint32_t b0, uint32_t b1) {
    asm volatile(
        "mma.sync.aligned.m16n8k8.row.col.f32.tf32.tf32.f32 "
        "{%0,%1,%2,%3}, {%4,%5,%6,%7}, {%8,%9}, {%0,%1,%2,%3};\n"
        : "+f"(d0), "+f"(d1), "+f"(d2), "+f"(d3)
        : "r"(a0), "r"(a1), "r"(a2), "r"(a3), "r"(b0), "r"(b1));
}

// ---------------- kernel 6: split-K tf32 tensor-core GEMM  P = A @ w1^T ----------------
// block tile: M=64, N=200 (25 n8-frags), Kchunk=512 (16 slabs of 32)
// 8 warps: warpM = wid&3 (16 rows each), warpN = wid>>2 (frags 0..12 / 13..24)
#define GM_BM 64
#define SASTR 36   // word stride; bank(lane)=lane for all frag loads; 36*4=144 (16B aligned)
__global__ void __launch_bounds__(256) gemm_tc_kernel(const float* __restrict__ w1) {
    const int M = g_M[0];
    const int mBase = blockIdx.y * GM_BM;
    if (mBase >= M) return;
    const int k0 = blockIdx.x * KCHUNK;
    __shared__ __align__(16) float sA[GM_BM * SASTR];
    __shared__ __align__(16) float sW[H1 * SASTR];
    const int tid = threadIdx.x;
    const int lane = tid & 31, wid = tid >> 5;
    const int warpM = wid & 3;
    const int nfBase = (wid >> 2) ? 13 : 0;

    float acc[13][4];
#pragma unroll
    for (int i = 0; i < 13; i++)
#pragma unroll
        for (int j = 0; j < 4; j++) acc[i][j] = 0.f;

    for (int slab = 0; slab < 16; slab++) {
        __syncthreads();
        // stage A: 64 rows x 32 k = 512 float4
#pragma unroll
        for (int u = 0; u < 2; u++) {
            int idx = tid + u * 256;
            int r = idx >> 3, kq = idx & 7;
            int g = mBase + r;
            float4 v = make_float4(0.f, 0.f, 0.f, 0.f);
            if (g < M)
                v = *reinterpret_cast<const float4*>(&g_A[(size_t)g * DD + k0 + slab * 32 + kq * 4]);
            cvt4(v);
            *reinterpret_cast<float4*>(&sA[r * SASTR + kq * 4]) = v;
        }
        // stage W: 200 rows x 32 k = 1600 float4
        for (int idx = tid; idx < H1 * 8; idx += 256) {
            int n = idx >> 3, kq = idx & 7;
            float4 v = *reinterpret_cast<const float4*>(&w1[(size_t)n * DD + k0 + slab * 32 + kq * 4]);
            cvt4(v);
            *reinterpret_cast<float4*>(&sW[n * SASTR + kq * 4]) = v;
        }
        __syncthreads();
#pragma unroll
        for (int ks = 0; ks < 4; ks++) {
            int kcol = ks * 8 + (lane & 3);
            int row0 = warpM * 16 + (lane >> 2);
            uint32_t a0 = __float_as_uint(sA[row0 * SASTR + kcol]);
            uint32_t a1 = __float_as_uint(sA[(row0 + 8) * SASTR + kcol]);
            uint32_t a2 = __float_as_uint(sA[row0 * SASTR + kcol + 4]);
            uint32_t a3 = __float_as_uint(sA[(row0 + 8) * SASTR + kcol + 4]);
#pragma unroll
            for (int nf = 0; nf < 13; nf++) {
                if (nfBase + nf < 25) {
                    int n0 = (nfBase + nf) * 8 + (lane >> 2);
                    uint32_t b0 = __float_as_uint(sW[n0 * SASTR + kcol]);
                    uint32_t b1 = __float_as_uint(sW[n0 * SASTR + kcol + 4]);
                    mma_tf32(acc[nf][0], acc[nf][1], acc[nf][2], acc[nf][3],
                             a0, a1, a2, a3, b0, b1);
                }
            }
        }
    }
    // epilogue: write partials
    int rowA = mBase + warpM * 16 + (lane >> 2);
    int rowB = rowA + 8;
#pragma unroll
    for (int nf = 0; nf < 13; nf++) {
        if (nfBase + nf < 25) {
            int col = (nfBase + nf) * 8 + (lane & 3) * 2;
            if (rowA < MAXROWS)
                *reinterpret_cast<float2*>(&g_P[((size_t)blockIdx.x * MAXROWS + rowA) * H1 + col]) =
                    make_float2(acc[nf][0], acc[nf][1]);
            if (rowB < MAXROWS)
                *reinterpret_cast<float2*>(&g_P[((size_t)blockIdx.x * MAXROWS + rowB) * H1 + col]) =
                    make_float2(acc[nf][2], acc[nf][3]);
        }
    }
}

// ---------------- kernel 7: reduce split-K + bias + relu ----------------
__global__ void reduce1_kernel(const float* __restrict__ b1) {
    int idx = blockIdx.x * blockDim.x + threadIdx.x;
    if (idx >= NTOT * H1) return;
    int r = idx / H1;
    if (r >= g_M[0]) return;
    int o = idx % H1;
    float s = b1[o];
#pragma unroll
    for (int ks = 0; ks < KSPLIT; ks++)
        s += g_P[((size_t)ks * MAXROWS + r) * H1 + o];
    g_h1[idx] = fmaxf(s, 0.f);
}

// ---------------- kernel 8: small MLP tail per unique row ----------------
__global__ void mlp_kernel(const float* __restrict__ w2, const float* __restrict__ b2,
                           const float* __restrict__ w3, const float* __restrict__ b3,
                           const float* __restrict__ w4, const float* __restrict__ b4) {
    int r = blockIdx.x;
    if (r >= g_M[0]) return;
    __shared__ float h1s[H1];
    __shared__ float h2s[H2];
    for (int k = threadIdx.x; k < H1; k += 128) h1s[k] = g_h1[r * H1 + k];
    __syncthreads();
    int t = threadIdx.x;
    if (t < H2) {
        float s = b2[t];
        const float* wr = w2 + t * H1;
#pragma unroll 4
        for (int k = 0; k < H1; k++) s += h1s[k] * wr[k];
        h2s[t] = fmaxf(s, 0.f);
    }
    __syncthreads();
    if (t < 85) {
        float s;
        const float* wr;
        if (t < KC) { s = b3[t];      wr = w3 + t * H2; }
        else        { s = b4[t - KC]; wr = w4 + (t - KC) * H2; }
#pragma unroll 4
        for (int k = 0; k < H2; k++) s += h2s[k] * wr[k];
        g_out85[r * 85 + t] = s;
    }
}

// ---------------- kernel 9: scatter unique rows to all ROIs ----------------
__global__ void scatter_kernel(float* __restrict__ out) {
    int idx = blockIdx.x * blockDim.x + threadIdx.x;
    if (idx >= NTOT * 85) return;
    int bn = idx / 85;
    int q = idx % 85;
    int r = g_roiRow[bn];
    float val = g_out85[r * 85 + q];
    if (q < KC) {
        out[bn * KC + q] = val;                            // z1: (B,A,G,G,17)
    } else {
        int k = (q - KC) / KC, cls = (q - KC) % KC;
        int b = bn / NROI, n = bn % NROI;
        out[NTOT * KC + (((b * 4 + k) * NROI + n) * KC + cls)] = val;  // z3: (B,4,A,G,G,17)
    }
}

// ---------------- launch ----------------
extern "C" void kernel_launch(void* const* d_in, const int* in_sizes, int n_in,
                              void* d_out, int out_size) {
    const float* cfeats = (const float*)d_in[0];
    const float* regcls = (const float*)d_in[1];
    const float* wan    = (const float*)d_in[2];
    const float* han    = (const float*)d_in[3];
    const float* xan    = (const float*)d_in[4];
    const float* yan    = (const float*)d_in[5];
    const float* w1     = (const float*)d_in[6];
    const float* b1     = (const float*)d_in[7];
    const float* w2     = (const float*)d_in[8];
    const float* b2     = (const float*)d_in[9];
    const float* w3     = (const float*)d_in[10];
    const float* b3     = (const float*)d_in[11];
    const float* w4     = (const float*)d_in[12];
    const float* b4     = (const float*)d_in[13];
    float* out = (float*)d_out;

    zero_kernel<<<(TOTKEY + 255) / 256, 256>>>();
    boxes_kernel<<<(NTOT + 255) / 256, 256>>>(regcls, wan, han, xan, yan);
    compact_kernel<<<1, 1024>>>();
    assign_kernel<<<(NTOT + 255) / 256, 256>>>();
    pool_kernel<<<MAXROWS, 256>>>(cfeats);
    {
        dim3 grid(KSPLIT, (MAXROWS + GM_BM - 1) / GM_BM);
        gemm_tc_kernel<<<grid, 256>>>(w1);
    }
    reduce1_kernel<<<(NTOT * H1 + 255) / 256, 256>>>(b1);
    mlp_kernel<<<MAXROWS, 128>>>(w2, b2, w3, b3, w4, b4);
    scatter_kernel<<<(NTOT * 85 + 255) / 256, 256>>>(out);
}